// round 2
// baseline (speedup 1.0000x reference)
#include <cuda_runtime.h>
#include <cuda_fp16.h>

typedef unsigned long long ull;

// ---------------- static scratch ----------------
__device__ __align__(16) __half g_xn[(size_t)32768 * 1024];     // 64 MB fp16 normalized x
__device__ __align__(16) float  g_sim[8 * 16 * 4096];           // logits
__device__ __align__(16) float2 g_att2[(size_t)8 * 4096 * 16];  // attn duplicated {p,p}, [b][s][h]
__device__ __align__(16) float  g_qn[16 * 64];
__device__ __align__(16) float  g_wq[16 * 1024];
__device__            float     g_kdot[16];
__device__ __align__(16) float  g_ypart[16 * 8 * 16 * 1024];    // [chunk][b][h][d]
__device__ __align__(16) float  g_y[8 * 16 * 1024];             // [b][h][d]
__device__ __align__(16) float  g_ohp[4 * 8 * 16 * 64];         // [dchunk][b][h][dh]

// ---------------- K0a: qn = ln(q) * dh^-0.5 ----------------
__global__ void k_qn(const float* __restrict__ q, const float* __restrict__ qg,
                     const float* __restrict__ qb) {
    int t = threadIdx.x, h = t >> 5, lane = t & 31;
    float v0 = q[h * 64 + lane];
    float v1 = q[h * 64 + 32 + lane];
    float s = v0 + v1, ss = v0 * v0 + v1 * v1;
#pragma unroll
    for (int k = 16; k >= 1; k >>= 1) {
        s  += __shfl_xor_sync(0xffffffffu, s, k);
        ss += __shfl_xor_sync(0xffffffffu, ss, k);
    }
    float mu = s * (1.0f / 64.0f);
    float var = ss * (1.0f / 64.0f) - mu * mu;
    float rs = rsqrtf(var + 1e-5f);
    g_qn[h * 64 + lane]      = ((v0 - mu) * rs * qg[lane]      + qb[lane])      * 0.125f;
    g_qn[h * 64 + 32 + lane] = ((v1 - mu) * rs * qg[32 + lane] + qb[32 + lane]) * 0.125f;
}

// ---------------- K0b: wq[h][d] = qn[h] . Wkv[d, h*64 : h*64+64]; kdot[h] = qn[h].bk[h]
__global__ void k_wq(const float* __restrict__ Wkv, const float* __restrict__ bkv) {
    int gt = blockIdx.x * 256 + threadIdx.x;  // 16384
    int h = gt >> 10, d = gt & 1023;
    const float4* wr = (const float4*)(Wkv + (size_t)d * 2048 + h * 64);
    const float4* qn = (const float4*)(g_qn + h * 64);
    float acc = 0.f;
#pragma unroll
    for (int i = 0; i < 16; i++) {
        float4 a = __ldg(wr + i);
        float4 b = __ldg(qn + i);
        acc += a.x * b.x + a.y * b.y + a.z * b.z + a.w * b.w;
    }
    g_wq[h * 1024 + d] = acc;
    if (d == 0) {
        float kd = 0.f;
#pragma unroll 8
        for (int i = 0; i < 64; i++) kd += g_qn[h * 64 + i] * __ldg(bkv + h * 64 + i);
        g_kdot[h] = kd;
    }
}

// ---------------- butterfly: 16 partial sums across a warp ----------------
template <int K>
__device__ __forceinline__ void bstep(float (&acc)[16], int lane) {
    bool up = (lane & K) != 0;
#pragma unroll
    for (int i = 0; i < K; i++) {
        float snd = up ? acc[i] : acc[i + K];
        float oth = __shfl_xor_sync(0xffffffffu, snd, K);
        acc[i] = (up ? acc[i + K] : acc[i]) + oth;
    }
}

// ---------------- K1: LN(x) -> xn(fp16) + sim = xn . wq, fused -----------------
// 1024 blocks x 256 threads, 32 rows/block (4 chunks of 8). Thread t owns cols 4t..4t+3.
__global__ __launch_bounds__(256, 2) void k_main(const float* __restrict__ x,
                                                 const float* __restrict__ ng,
                                                 const float* __restrict__ nb) {
    int t = threadIdx.x, w = t >> 5, lane = t & 31;
    __shared__ float s_st[8][8][2];
    __shared__ float s_mr[8][2];
    __shared__ float s_sim[8][8][16];

    float4 wq4[16];
#pragma unroll
    for (int h = 0; h < 16; h++) wq4[h] = __ldg((const float4*)(g_wq + h * 1024) + t);
    float4 g4 = __ldg((const float4*)ng + t);
    float4 b4 = __ldg((const float4*)nb + t);

    int rowblock = blockIdx.x * 32;
    const float4* xb = (const float4*)x + (size_t)rowblock * 256;

    for (int c = 0; c < 4; c++) {
        float sm[8], sq[8];
#pragma unroll
        for (int r = 0; r < 8; r++) {
            float4 v = __ldcs(xb + (size_t)(c * 8 + r) * 256 + t);
            sm[r] = v.x + v.y + v.z + v.w;
            sq[r] = v.x * v.x + v.y * v.y + v.z * v.z + v.w * v.w;
        }
#pragma unroll
        for (int r = 0; r < 8; r++) {
#pragma unroll
            for (int k = 16; k >= 1; k >>= 1) {
                sm[r] += __shfl_xor_sync(0xffffffffu, sm[r], k);
                sq[r] += __shfl_xor_sync(0xffffffffu, sq[r], k);
            }
        }
        if (lane == 0) {
#pragma unroll
            for (int r = 0; r < 8; r++) { s_st[w][r][0] = sm[r]; s_st[w][r][1] = sq[r]; }
        }
        __syncthreads();
        if (t < 8) {
            float S = 0.f, Q = 0.f;
#pragma unroll
            for (int w2 = 0; w2 < 8; w2++) { S += s_st[w2][t][0]; Q += s_st[w2][t][1]; }
            float m = S * (1.0f / 1024.0f);
            float var = Q * (1.0f / 1024.0f) - m * m;
            s_mr[t][0] = m;
            s_mr[t][1] = rsqrtf(var + 1e-5f);
        }
        __syncthreads();

#pragma unroll
        for (int r = 0; r < 8; r++) {
            float mu = s_mr[r][0], rs = s_mr[r][1];
            float4 v = __ldcs(xb + (size_t)(c * 8 + r) * 256 + t);  // L1 hit
            float4 xnv;
            xnv.x = (v.x - mu) * rs * g4.x + b4.x;
            xnv.y = (v.y - mu) * rs * g4.y + b4.y;
            xnv.z = (v.z - mu) * rs * g4.z + b4.z;
            xnv.w = (v.w - mu) * rs * g4.w + b4.w;

            size_t row = (size_t)rowblock + c * 8 + r;
            __half2 p01 = __floats2half2_rn(xnv.x, xnv.y);
            __half2 p23 = __floats2half2_rn(xnv.z, xnv.w);
            uint2 pk;
            pk.x = *reinterpret_cast<unsigned*>(&p01);
            pk.y = *reinterpret_cast<unsigned*>(&p23);
            *reinterpret_cast<uint2*>(g_xn + row * 1024 + 4 * t) = pk;

            float acc[16];
#pragma unroll
            for (int h = 0; h < 16; h++)
                acc[h] = xnv.x * wq4[h].x + xnv.y * wq4[h].y + xnv.z * wq4[h].z +
                         xnv.w * wq4[h].w;
            bstep<8>(acc, lane);
            bstep<4>(acc, lane);
            bstep<2>(acc, lane);
            bstep<1>(acc, lane);
            acc[0] += __shfl_xor_sync(0xffffffffu, acc[0], 16);
            if (lane < 16) s_sim[r][w][lane] = acc[0];
        }
        __syncthreads();

        if (t < 128) {
            int r = t >> 4, h = t & 15;
            float v = 0.f;
#pragma unroll
            for (int w2 = 0; w2 < 8; w2++) v += s_sim[r][w2][h];
            int row = rowblock + c * 8 + r;
            int b = row >> 12, s = row & 4095;
            g_sim[((size_t)(b * 16 + h)) * 4096 + s] = v + g_kdot[h];
        }
        __syncthreads();
    }
}

// ---------------- K2: softmax over s per (b,h); write attn + duplicated transpose ---
__global__ void k_softmax(float* __restrict__ attn_out) {
    int bh = blockIdx.x, t = threadIdx.x, w = t >> 5, lane = t & 31;
    const float* sr = g_sim + (size_t)bh * 4096;
    float v[16];
    float mx = -1e30f;
#pragma unroll
    for (int k = 0; k < 16; k++) { v[k] = sr[k * 256 + t]; mx = fmaxf(mx, v[k]); }
#pragma unroll
    for (int k = 16; k >= 1; k >>= 1) mx = fmaxf(mx, __shfl_xor_sync(0xffffffffu, mx, k));
    __shared__ float red[8];
    if (lane == 0) red[w] = mx;
    __syncthreads();
    float bm = red[0];
#pragma unroll
    for (int i = 1; i < 8; i++) bm = fmaxf(bm, red[i]);
    __syncthreads();
    float s = 0.f;
#pragma unroll
    for (int k = 0; k < 16; k++) { v[k] = __expf(v[k] - bm); s += v[k]; }
#pragma unroll
    for (int k = 16; k >= 1; k >>= 1) s += __shfl_xor_sync(0xffffffffu, s, k);
    if (lane == 0) red[w] = s;
    __syncthreads();
    float tot = 0.f;
#pragma unroll
    for (int i = 0; i < 8; i++) tot += red[i];
    float inv = 1.0f / tot;
    int b = bh >> 4, h = bh & 15;
#pragma unroll
    for (int k = 0; k < 16; k++) {
        float p = v[k] * inv;
        int sdx = k * 256 + t;
        attn_out[(size_t)bh * 4096 + sdx] = p;
        g_att2[((size_t)(b * 4096 + sdx)) * 16 + h] = make_float2(p, p);
    }
}

__device__ __forceinline__ ull ffma2(ull a, ull b, ull c) {
    ull d;
    asm("fma.rn.f32x2 %0, %1, %2, %3;" : "=l"(d) : "l"(a), "l"(b), "l"(c));
    return d;
}

// ---------------- K3: y_part[chunk][b][h][d] = sum_{s in chunk} attn * xn ----------
// grid 128 = (b, s-chunk of 256); 256 threads; thread owns cols 4t..4t+3, all 16 heads.
__global__ __launch_bounds__(256) void k_y() {
    int b = blockIdx.x >> 4, ch = blockIdx.x & 15;
    int t = threadIdx.x;
    int s0 = ch * 256;
    const __half* xrow = g_xn + ((size_t)(b * 4096 + s0)) * 1024 + 4 * t;
    const ulonglong2* attb = (const ulonglong2*)g_att2 + ((size_t)(b * 4096 + s0)) * 8;
    ull accA[16], accB[16];
#pragma unroll
    for (int h = 0; h < 16; h++) { accA[h] = 0ull; accB[h] = 0ull; }
    for (int s = 0; s < 256; s++) {
        uint2 px = *reinterpret_cast<const uint2*>(xrow + (size_t)s * 1024);
        __half2 h01 = *reinterpret_cast<__half2*>(&px.x);
        __half2 h23 = *reinterpret_cast<__half2*>(&px.y);
        float2 f01 = __half22float2(h01), f23 = __half22float2(h23);
        ull x01, x23;
        asm("mov.b64 %0, {%1, %2};" : "=l"(x01) : "f"(f01.x), "f"(f01.y));
        asm("mov.b64 %0, {%1, %2};" : "=l"(x23) : "f"(f23.x), "f"(f23.y));
#pragma unroll
        for (int j = 0; j < 8; j++) {
            ulonglong2 u = __ldg(&attb[(size_t)s * 8 + j]);
            accA[2 * j]     = ffma2(x01, u.x, accA[2 * j]);
            accB[2 * j]     = ffma2(x23, u.x, accB[2 * j]);
            accA[2 * j + 1] = ffma2(x01, u.y, accA[2 * j + 1]);
            accB[2 * j + 1] = ffma2(x23, u.y, accB[2 * j + 1]);
        }
    }
    float* yp = g_ypart + ((size_t)(ch * 8 + b) * 16) * 1024 + 4 * t;
#pragma unroll
    for (int h = 0; h < 16; h++) {
        float4 o;
        asm("mov.b64 {%0, %1}, %2;" : "=f"(o.x), "=f"(o.y) : "l"(accA[h]));
        asm("mov.b64 {%0, %1}, %2;" : "=f"(o.z), "=f"(o.w) : "l"(accB[h]));
        *reinterpret_cast<float4*>(yp + (size_t)h * 1024) = o;
    }
}

// ---------------- K3r: reduce 16 s-chunk partials ----------------
__global__ void k_yred() {
    int i4 = blockIdx.x * 256 + threadIdx.x;  // 32768 float4
    float4 acc = make_float4(0.f, 0.f, 0.f, 0.f);
#pragma unroll
    for (int c = 0; c < 16; c++) {
        float4 v = ((const float4*)g_ypart)[(size_t)c * 32768 + i4];
        acc.x += v.x; acc.y += v.y; acc.z += v.z; acc.w += v.w;
    }
    ((float4*)g_y)[i4] = acc;
}

// ---------------- K4: oh_part[dc][b][h][dh] = sum_{d in chunk} y[b,h,d]*Wv[d][h,dh]
__global__ void k_oh(const float* __restrict__ Wkv) {
    int t = threadIdx.x, w = t >> 5, lane = t & 31;
    int wg = blockIdx.x * 8 + w;  // 0..511
    int dc = wg >> 7;
    int bh = wg & 127;
    int h = bh & 15;
    const float* yrow = g_y + (size_t)bh * 1024;
    float2 acc = make_float2(0.f, 0.f);
    int d0 = dc * 256;
#pragma unroll 4
    for (int d = 0; d < 256; d++) {
        int dd = d0 + d;
        float yv = __ldg(yrow + dd);
        float2 wv = *reinterpret_cast<const float2*>(Wkv + (size_t)dd * 2048 + 1024 + h * 64 + lane * 2);
        acc.x += yv * wv.x;
        acc.y += yv * wv.y;
    }
    *reinterpret_cast<float2*>(g_ohp + (size_t)(dc * 128 + bh) * 64 + lane * 2) = acc;
}

// ---------------- K5: out[b][d] = oh[b] . Wout[:,d] + bout[d] ----------------
__global__ void k_out(const float* __restrict__ Wout, const float* __restrict__ bout,
                      const float* __restrict__ bkv, float* __restrict__ out) {
    __shared__ float s_oh[8192];
    int t = threadIdx.x;
#pragma unroll
    for (int j = 0; j < 32; j++) {
        int idx = j * 256 + t;
        float v = g_ohp[idx] + g_ohp[8192 + idx] + g_ohp[16384 + idx] + g_ohp[24576 + idx];
        v += __ldg(bkv + 1024 + (idx & 1023));  // V bias passes through (attn sums to 1)
        s_oh[idx] = v;
    }
    __syncthreads();
    int b = t >> 5, dl = t & 31;
    int d = blockIdx.x * 32 + dl;
    float acc = 0.f;
#pragma unroll 8
    for (int i = 0; i < 1024; i++)
        acc += s_oh[b * 1024 + i] * __ldg(Wout + (size_t)i * 1024 + d);
    out[b * 1024 + d] = acc + __ldg(bout + d);
}

// ---------------- launch ----------------
extern "C" void kernel_launch(void* const* d_in, const int* in_sizes, int n_in,
                              void* d_out, int out_size) {
    const float* x    = (const float*)d_in[0];
    const float* q    = (const float*)d_in[1];
    const float* Wkv  = (const float*)d_in[2];
    const float* bkv  = (const float*)d_in[3];
    const float* Wout = (const float*)d_in[4];
    const float* bout = (const float*)d_in[5];
    const float* ng   = (const float*)d_in[6];
    const float* nb   = (const float*)d_in[7];
    const float* qg   = (const float*)d_in[8];
    const float* qb   = (const float*)d_in[9];
    float* out = (float*)d_out;          // [8,1,1024] = 8192 floats
    float* attn = out + 8192;            // [8,16,1,4096] = 524288 floats

    k_qn<<<1, 512>>>(q, qg, qb);
    k_wq<<<64, 256>>>(Wkv, bkv);
    k_main<<<1024, 256>>>(x, ng, nb);
    k_softmax<<<128, 256>>>(attn);
    k_y<<<128, 256>>>();
    k_yred<<<128, 256>>>();
    k_oh<<<64, 256>>>(Wkv);
    k_out<<<32, 256>>>(Wout, bout, bkv, out);
}

// round 3
// speedup vs baseline: 1.4419x; 1.4419x over previous
#include <cuda_runtime.h>
#include <cuda_fp16.h>

typedef unsigned long long ull;

// ---------------- static scratch ----------------
__device__ __align__(16) __half g_xn[(size_t)32768 * 1024];     // 64 MB fp16 normalized x
__device__ __align__(16) float  g_sim[8 * 16 * 4096];           // logits
__device__ __align__(16) float2 g_att2[(size_t)8 * 4096 * 16];  // attn duplicated {p,p}, [b][s][h]
__device__ __align__(16) float  g_qn[16 * 64];
__device__ __align__(16) float  g_wq[16 * 1024];
__device__            float     g_kdot[16];
__device__ __align__(16) float  g_ypart[16 * 8 * 16 * 1024];    // [chunk][b][h][d]
__device__ __align__(16) float  g_y[8 * 16 * 1024];             // [b][h][d]
__device__ __align__(16) float  g_ohp[8 * 8 * 16 * 64];         // [dchunk][b][h][dh]
__device__ __align__(16) float  g_oh[8 * 1024];                 // [b][inner]
__device__ __align__(16) float  g_outp[8 * 8 * 1024];           // [ichunk][b][d]

// ---------------- K0a: qn = ln(q) * dh^-0.5 ----------------
__global__ void k_qn(const float* __restrict__ q, const float* __restrict__ qg,
                     const float* __restrict__ qb) {
    int t = threadIdx.x, h = t >> 5, lane = t & 31;
    float v0 = q[h * 64 + lane];
    float v1 = q[h * 64 + 32 + lane];
    float s = v0 + v1, ss = v0 * v0 + v1 * v1;
#pragma unroll
    for (int k = 16; k >= 1; k >>= 1) {
        s  += __shfl_xor_sync(0xffffffffu, s, k);
        ss += __shfl_xor_sync(0xffffffffu, ss, k);
    }
    float mu = s * (1.0f / 64.0f);
    float var = ss * (1.0f / 64.0f) - mu * mu;
    float rs = rsqrtf(var + 1e-5f);
    g_qn[h * 64 + lane]      = ((v0 - mu) * rs * qg[lane]      + qb[lane])      * 0.125f;
    g_qn[h * 64 + 32 + lane] = ((v1 - mu) * rs * qg[32 + lane] + qb[32 + lane]) * 0.125f;
}

// ---------------- K0b: wq[h][d] = qn[h] . Wkv[d, h*64:h*64+64]; kdot[h] = qn[h].bk[h]
__global__ void k_wq(const float* __restrict__ Wkv, const float* __restrict__ bkv) {
    int gt = blockIdx.x * 256 + threadIdx.x;  // 16384
    int h = gt >> 10, d = gt & 1023;
    const float4* wr = (const float4*)(Wkv + (size_t)d * 2048 + h * 64);
    const float4* qn = (const float4*)(g_qn + h * 64);
    float acc = 0.f;
#pragma unroll
    for (int i = 0; i < 16; i++) {
        float4 a = __ldg(wr + i);
        float4 b = __ldg(qn + i);
        acc += a.x * b.x + a.y * b.y + a.z * b.z + a.w * b.w;
    }
    g_wq[h * 1024 + d] = acc;
    if (d == 0) {
        float kd = 0.f;
#pragma unroll 8
        for (int i = 0; i < 64; i++) kd += g_qn[h * 64 + i] * __ldg(bkv + h * 64 + i);
        g_kdot[h] = kd;
    }
}

// ---------------- butterfly: 16 partial sums across a warp ----------------
template <int K>
__device__ __forceinline__ void bstep(float (&acc)[16], int lane) {
    bool up = (lane & K) != 0;
#pragma unroll
    for (int i = 0; i < K; i++) {
        float snd = up ? acc[i] : acc[i + K];
        float oth = __shfl_xor_sync(0xffffffffu, snd, K);
        acc[i] = (up ? acc[i + K] : acc[i]) + oth;
    }
}

// ---------------- K1: LN(x) -> xn(fp16) + sim = xn . wq, fused -----------------
// 1024 blocks x 256 threads, 32 rows/block (4 chunks of 8). Thread t owns cols 4t..4t+3.
// Loads are default (cache-all) so the phase-B re-read is an L1 hit.
__global__ __launch_bounds__(256, 2) void k_main(const float* __restrict__ x,
                                                 const float* __restrict__ ng,
                                                 const float* __restrict__ nb) {
    int t = threadIdx.x, w = t >> 5, lane = t & 31;
    __shared__ float s_st[8][8][2];
    __shared__ float s_mr[8][2];
    __shared__ float s_sim[8][8][16];

    float4 wq4[16];
#pragma unroll
    for (int h = 0; h < 16; h++) wq4[h] = __ldg((const float4*)(g_wq + h * 1024) + t);
    float4 g4 = __ldg((const float4*)ng + t);
    float4 b4 = __ldg((const float4*)nb + t);

    int rowblock = blockIdx.x * 32;
    const float4* xb = (const float4*)x + (size_t)rowblock * 256;

    for (int c = 0; c < 4; c++) {
        float sm[8], sq[8];
#pragma unroll
        for (int r = 0; r < 8; r++) {
            float4 v = xb[(size_t)(c * 8 + r) * 256 + t];
            sm[r] = v.x + v.y + v.z + v.w;
            sq[r] = v.x * v.x + v.y * v.y + v.z * v.z + v.w * v.w;
        }
#pragma unroll
        for (int r = 0; r < 8; r++) {
#pragma unroll
            for (int k = 16; k >= 1; k >>= 1) {
                sm[r] += __shfl_xor_sync(0xffffffffu, sm[r], k);
                sq[r] += __shfl_xor_sync(0xffffffffu, sq[r], k);
            }
        }
        if (lane == 0) {
#pragma unroll
            for (int r = 0; r < 8; r++) { s_st[w][r][0] = sm[r]; s_st[w][r][1] = sq[r]; }
        }
        __syncthreads();
        if (t < 8) {
            float S = 0.f, Q = 0.f;
#pragma unroll
            for (int w2 = 0; w2 < 8; w2++) { S += s_st[w2][t][0]; Q += s_st[w2][t][1]; }
            float m = S * (1.0f / 1024.0f);
            float var = Q * (1.0f / 1024.0f) - m * m;
            s_mr[t][0] = m;
            s_mr[t][1] = rsqrtf(var + 1e-5f);
        }
        __syncthreads();

#pragma unroll
        for (int r = 0; r < 8; r++) {
            float mu = s_mr[r][0], rs = s_mr[r][1];
            float4 v = xb[(size_t)(c * 8 + r) * 256 + t];  // L1 hit
            float4 xnv;
            xnv.x = (v.x - mu) * rs * g4.x + b4.x;
            xnv.y = (v.y - mu) * rs * g4.y + b4.y;
            xnv.z = (v.z - mu) * rs * g4.z + b4.z;
            xnv.w = (v.w - mu) * rs * g4.w + b4.w;

            size_t row = (size_t)rowblock + c * 8 + r;
            __half2 p01 = __floats2half2_rn(xnv.x, xnv.y);
            __half2 p23 = __floats2half2_rn(xnv.z, xnv.w);
            uint2 pk;
            pk.x = *reinterpret_cast<unsigned*>(&p01);
            pk.y = *reinterpret_cast<unsigned*>(&p23);
            *reinterpret_cast<uint2*>(g_xn + row * 1024 + 4 * t) = pk;

            float acc[16];
#pragma unroll
            for (int h = 0; h < 16; h++)
                acc[h] = xnv.x * wq4[h].x + xnv.y * wq4[h].y + xnv.z * wq4[h].z +
                         xnv.w * wq4[h].w;
            bstep<8>(acc, lane);
            bstep<4>(acc, lane);
            bstep<2>(acc, lane);
            bstep<1>(acc, lane);
            acc[0] += __shfl_xor_sync(0xffffffffu, acc[0], 16);
            if (lane < 16) s_sim[r][w][lane] = acc[0];
        }
        __syncthreads();

        if (t < 128) {
            int r = t >> 4, h = t & 15;
            float v = 0.f;
#pragma unroll
            for (int w2 = 0; w2 < 8; w2++) v += s_sim[r][w2][h];
            int row = rowblock + c * 8 + r;
            int b = row >> 12, s = row & 4095;
            g_sim[((size_t)(b * 16 + h)) * 4096 + s] = v + g_kdot[h];
        }
        __syncthreads();
    }
}

// ---------------- K2: softmax over s per (b,h); write attn + duplicated transpose ---
__global__ void k_softmax(float* __restrict__ attn_out) {
    int bh = blockIdx.x, t = threadIdx.x, w = t >> 5, lane = t & 31;
    const float* sr = g_sim + (size_t)bh * 4096;
    float v[16];
    float mx = -1e30f;
#pragma unroll
    for (int k = 0; k < 16; k++) { v[k] = sr[k * 256 + t]; mx = fmaxf(mx, v[k]); }
#pragma unroll
    for (int k = 16; k >= 1; k >>= 1) mx = fmaxf(mx, __shfl_xor_sync(0xffffffffu, mx, k));
    __shared__ float red[8];
    if (lane == 0) red[w] = mx;
    __syncthreads();
    float bm = red[0];
#pragma unroll
    for (int i = 1; i < 8; i++) bm = fmaxf(bm, red[i]);
    __syncthreads();
    float s = 0.f;
#pragma unroll
    for (int k = 0; k < 16; k++) { v[k] = __expf(v[k] - bm); s += v[k]; }
#pragma unroll
    for (int k = 16; k >= 1; k >>= 1) s += __shfl_xor_sync(0xffffffffu, s, k);
    if (lane == 0) red[w] = s;
    __syncthreads();
    float tot = 0.f;
#pragma unroll
    for (int i = 0; i < 8; i++) tot += red[i];
    float inv = 1.0f / tot;
    int b = bh >> 4, h = bh & 15;
#pragma unroll
    for (int k = 0; k < 16; k++) {
        float p = v[k] * inv;
        int sdx = k * 256 + t;
        attn_out[(size_t)bh * 4096 + sdx] = p;
        g_att2[((size_t)(b * 4096 + sdx)) * 16 + h] = make_float2(p, p);
    }
}

__device__ __forceinline__ ull ffma2(ull a, ull b, ull c) {
    ull d;
    asm("fma.rn.f32x2 %0, %1, %2, %3;" : "=l"(d) : "l"(a), "l"(b), "l"(c));
    return d;
}

// ---------------- K3: y_part[ch][b][h][d] = sum_{s in chunk} attn * xn -------------
// grid 256 = b(8) x ch(16) x hg(2); 256 threads; thread owns cols 4t..4t+3, 8 heads.
// Per s-iter: 1 LDG.64 (x) + 4 LDG.128 (att, warp-uniform) + 16 FFMA2.
__global__ __launch_bounds__(256) void k_y() {
    int bid = blockIdx.x;
    int hg = bid & 1, ch = (bid >> 1) & 15, b = bid >> 5;
    int t = threadIdx.x;
    int s0 = ch * 256;
    const __half* xrow = g_xn + ((size_t)(b * 4096 + s0)) * 1024 + 4 * t;
    const ulonglong2* attb =
        (const ulonglong2*)(g_att2 + ((size_t)(b * 4096 + s0)) * 16 + hg * 8);
    ull accA[8], accB[8];
#pragma unroll
    for (int j = 0; j < 8; j++) { accA[j] = 0ull; accB[j] = 0ull; }
#pragma unroll 2
    for (int s = 0; s < 256; s++) {
        uint2 px = *reinterpret_cast<const uint2*>(xrow + (size_t)s * 1024);
        __half2 h01 = *reinterpret_cast<__half2*>(&px.x);
        __half2 h23 = *reinterpret_cast<__half2*>(&px.y);
        float2 f01 = __half22float2(h01), f23 = __half22float2(h23);
        ull x01, x23;
        asm("mov.b64 %0, {%1, %2};" : "=l"(x01) : "f"(f01.x), "f"(f01.y));
        asm("mov.b64 %0, {%1, %2};" : "=l"(x23) : "f"(f23.x), "f"(f23.y));
#pragma unroll
        for (int j = 0; j < 4; j++) {
            ulonglong2 u = __ldg(&attb[(size_t)s * 8 + j]);
            accA[2 * j]     = ffma2(x01, u.x, accA[2 * j]);
            accB[2 * j]     = ffma2(x23, u.x, accB[2 * j]);
            accA[2 * j + 1] = ffma2(x01, u.y, accA[2 * j + 1]);
            accB[2 * j + 1] = ffma2(x23, u.y, accB[2 * j + 1]);
        }
    }
    float* yp = g_ypart + ((size_t)(ch * 8 + b) * 16 + hg * 8) * 1024 + 4 * t;
#pragma unroll
    for (int j = 0; j < 8; j++) {
        float4 o;
        asm("mov.b64 {%0, %1}, %2;" : "=f"(o.x), "=f"(o.y) : "l"(accA[j]));
        asm("mov.b64 {%0, %1}, %2;" : "=f"(o.z), "=f"(o.w) : "l"(accB[j]));
        *reinterpret_cast<float4*>(yp + (size_t)j * 1024) = o;
    }
}

// ---------------- K3r: reduce 16 s-chunk partials ----------------
__global__ void k_yred() {
    int i4 = blockIdx.x * 256 + threadIdx.x;  // 32768 float4
    float4 acc = make_float4(0.f, 0.f, 0.f, 0.f);
#pragma unroll
    for (int c = 0; c < 16; c++) {
        float4 v = ((const float4*)g_ypart)[(size_t)c * 32768 + i4];
        acc.x += v.x; acc.y += v.y; acc.z += v.z; acc.w += v.w;
    }
    ((float4*)g_y)[i4] = acc;
}

// ---------------- K4: oh_part[dc][b][h][dh] = sum_{d in 128-chunk} y*Wv ------------
// grid 128 blocks x 8 warps = 1024 warps: dc(8) x bh(128).
__global__ void k_oh(const float* __restrict__ Wkv) {
    int t = threadIdx.x, w = t >> 5, lane = t & 31;
    int wg = blockIdx.x * 8 + w;  // 0..1023
    int dc = wg >> 7;
    int bh = wg & 127;
    int h = bh & 15;
    const float* yrow = g_y + (size_t)bh * 1024 + dc * 128;
    const float* wvb = Wkv + 1024 + h * 64 + lane * 2 + (size_t)(dc * 128) * 2048;
    float2 acc = make_float2(0.f, 0.f);
#pragma unroll 8
    for (int d = 0; d < 128; d++) {
        float yv = __ldg(yrow + d);
        float2 wv = *reinterpret_cast<const float2*>(wvb + (size_t)d * 2048);
        acc.x += yv * wv.x;
        acc.y += yv * wv.y;
    }
    *reinterpret_cast<float2*>(g_ohp + (size_t)(dc * 128 + bh) * 64 + lane * 2) = acc;
}

// ---------------- K4r: oh[b][inner] = sum_dc ohp + bv (bias passes: attn sums to 1)
__global__ void k_ohred(const float* __restrict__ bkv) {
    int idx = blockIdx.x * 256 + threadIdx.x;  // 8192
    float v = 0.f;
#pragma unroll
    for (int dc = 0; dc < 8; dc++) v += g_ohp[dc * 8192 + idx];
    g_oh[idx] = v + __ldg(bkv + 1024 + (idx & 1023));
}

// ---------------- K5: out partials over i-chunks of 128 ----------------
// grid 256 = dblk(32) x ic(8); 256 threads: b = t>>5, dl = t&31.
__global__ void k_outp(const float* __restrict__ Wout) {
    __shared__ float s_oh[8][128];
    int t = threadIdx.x;
    int dblk = blockIdx.x >> 3, ic = blockIdx.x & 7;
    {
        int b = t >> 5, j = t & 31;
#pragma unroll
        for (int k = 0; k < 4; k++) s_oh[b][j * 4 + k] = g_oh[b * 1024 + ic * 128 + j * 4 + k];
    }
    __syncthreads();
    int b = t >> 5, dl = t & 31;
    int d = dblk * 32 + dl;
    const float* wb = Wout + (size_t)(ic * 128) * 1024 + d;
    float acc = 0.f;
#pragma unroll 8
    for (int i = 0; i < 128; i++) acc += s_oh[b][i] * __ldg(wb + (size_t)i * 1024);
    g_outp[(size_t)(ic * 8 + b) * 1024 + d] = acc;
}

// ---------------- K5r: out[b][d] = sum_ic outp + bout ----------------
__global__ void k_outred(const float* __restrict__ bout, float* __restrict__ out) {
    int idx = blockIdx.x * 256 + threadIdx.x;  // 8192
    int b = idx >> 10, d = idx & 1023;
    float v = 0.f;
#pragma unroll
    for (int ic = 0; ic < 8; ic++) v += g_outp[(size_t)(ic * 8 + b) * 1024 + d];
    out[idx] = v + __ldg(bout + d);
}

// ---------------- launch ----------------
extern "C" void kernel_launch(void* const* d_in, const int* in_sizes, int n_in,
                              void* d_out, int out_size) {
    const float* x    = (const float*)d_in[0];
    const float* q    = (const float*)d_in[1];
    const float* Wkv  = (const float*)d_in[2];
    const float* bkv  = (const float*)d_in[3];
    const float* Wout = (const float*)d_in[4];
    const float* bout = (const float*)d_in[5];
    const float* ng   = (const float*)d_in[6];
    const float* nb   = (const float*)d_in[7];
    const float* qg   = (const float*)d_in[8];
    const float* qb   = (const float*)d_in[9];
    float* out = (float*)d_out;          // [8,1,1024]
    float* attn = out + 8192;            // [8,16,1,4096]

    k_qn<<<1, 512>>>(q, qg, qb);
    k_wq<<<64, 256>>>(Wkv, bkv);
    k_main<<<1024, 256>>>(x, ng, nb);
    k_softmax<<<128, 256>>>(attn);
    k_y<<<256, 256>>>();
    k_yred<<<128, 256>>>();
    k_oh<<<128, 256>>>(Wkv);
    k_ohred<<<32, 256>>>(bkv);
    k_outp<<<256, 256>>>(Wout);
    k_outred<<<32, 256>>>(bout, out);
}

// round 4
// speedup vs baseline: 1.7064x; 1.1835x over previous
#include <cuda_runtime.h>
#include <cuda_fp16.h>

typedef unsigned long long ull;

// ---------------- static scratch ----------------
__device__ __align__(16) __half g_xn[(size_t)32768 * 1024];      // 64 MB fp16 normalized x
__device__ __align__(16) float  g_sim[8 * 16 * 4096];            // logits
__device__ __align__(16) float2 g_att2[(size_t)8 * 4096 * 16];   // attn dup {p,p}, [b][s][h]
__device__ __align__(16) float  g_qn[16 * 64];
__device__ __align__(16) ull    g_wqp[8 * 1024];                 // head-pair-interleaved wq
__device__            float     g_kdot[16];
__device__ __align__(16) float2 g_minv[128];                     // per (b,h): {max, inv}
__device__ __align__(16) float  g_ypart[32 * 8 * 16 * 1024];     // [chunk][b][h][d] 16MB
__device__ __align__(16) float  g_y[8 * 16 * 1024];              // [b][h][d]
__device__ __align__(16) float  g_ohp[8 * 8 * 16 * 64];          // [dchunk][b][h][dh]
__device__ __align__(16) float  g_outp[8 * 8 * 1024];            // [ichunk][b][d]

__device__ __forceinline__ ull ffma2(ull a, ull b, ull c) {
    ull d;
    asm("fma.rn.f32x2 %0, %1, %2, %3;" : "=l"(d) : "l"(a), "l"(b), "l"(c));
    return d;
}
__device__ __forceinline__ ull fdup(float v) {
    ull d;
    asm("mov.b64 %0, {%1, %1};" : "=l"(d) : "f"(v));
    return d;
}
__device__ __forceinline__ ull fpack(float lo, float hi) {
    ull d;
    asm("mov.b64 %0, {%1, %2};" : "=l"(d) : "f"(lo), "f"(hi));
    return d;
}
__device__ __forceinline__ void funpack(ull v, float& lo, float& hi) {
    asm("mov.b64 {%0, %1}, %2;" : "=f"(lo), "=f"(hi) : "l"(v));
}

// generic butterfly step: N-array partial reduce across lanes
template <int K, int N>
__device__ __forceinline__ void bstep(float (&acc)[N], int lane) {
    bool up = (lane & K) != 0;
#pragma unroll
    for (int i = 0; i < K; i++) {
        float snd = up ? acc[i] : acc[i + K];
        float oth = __shfl_xor_sync(0xffffffffu, snd, K);
        acc[i] = (up ? acc[i + K] : acc[i]) + oth;
    }
}

// ---------------- K0a: qn = ln(q) * dh^-0.5 ; kdot[h] = qn[h].bk[h] ----------------
__global__ void k_qn(const float* __restrict__ q, const float* __restrict__ qg,
                     const float* __restrict__ qb, const float* __restrict__ bkv) {
    int t = threadIdx.x, h = t >> 5, lane = t & 31;
    float v0 = q[h * 64 + lane];
    float v1 = q[h * 64 + 32 + lane];
    float s = v0 + v1, ss = v0 * v0 + v1 * v1;
#pragma unroll
    for (int k = 16; k >= 1; k >>= 1) {
        s  += __shfl_xor_sync(0xffffffffu, s, k);
        ss += __shfl_xor_sync(0xffffffffu, ss, k);
    }
    float mu = s * (1.0f / 64.0f);
    float var = ss * (1.0f / 64.0f) - mu * mu;
    float rs = rsqrtf(var + 1e-5f);
    float qn0 = ((v0 - mu) * rs * qg[lane]      + qb[lane])      * 0.125f;
    float qn1 = ((v1 - mu) * rs * qg[32 + lane] + qb[32 + lane]) * 0.125f;
    g_qn[h * 64 + lane]      = qn0;
    g_qn[h * 64 + 32 + lane] = qn1;
    float kd = qn0 * __ldg(bkv + h * 64 + lane) + qn1 * __ldg(bkv + h * 64 + 32 + lane);
#pragma unroll
    for (int k = 16; k >= 1; k >>= 1) kd += __shfl_xor_sync(0xffffffffu, kd, k);
    if (lane == 0) g_kdot[h] = kd;
}

// ---------------- K0b: warp per d — coalesced read of Wkv[d][0:1024] ----------------
// lane loads float4 at col 4*lane + 128*j -> head h = 2*j + (lane>=16).
// Writes g_wqp[j][d] = pack{wq[2j][d], wq[2j+1][d]}.
__global__ void k_wq(const float* __restrict__ Wkv) {
    int w = threadIdx.x >> 5, lane = threadIdx.x & 31;
    int d = blockIdx.x * 8 + w;
    const float4* wr = (const float4*)(Wkv + (size_t)d * 2048);
    const float4* qp = (const float4*)g_qn;
    float acc[8];
#pragma unroll
    for (int j = 0; j < 8; j++) {
        float4 a = __ldg(wr + j * 32 + lane);
        float4 b = __ldg(qp + j * 32 + lane);
        acc[j] = a.x * b.x + a.y * b.y + a.z * b.z + a.w * b.w;
    }
    bstep<4>(acc, lane);
    bstep<2>(acc, lane);
    bstep<1>(acc, lane);
    acc[0] += __shfl_xor_sync(0xffffffffu, acc[0], 8);  // now acc[0] = sum for pair j=lane&7, parity=lane>=16
    float odd = __shfl_sync(0xffffffffu, acc[0], (lane & 7) + 16);
    if (lane < 8) g_wqp[lane * 1024 + d] = fpack(acc[0], odd);
}

// ---------------- K1: LN(x) -> xn(fp16) + sim via f32x2 head-pair dots -------------
// 1024 blocks x 256 threads, 32 rows/block, 8 iterations of 4 rows. x kept in regs.
__global__ __launch_bounds__(256, 2) void k_main(const float* __restrict__ x,
                                                 const float* __restrict__ ng,
                                                 const float* __restrict__ nb) {
    int t = threadIdx.x, w = t >> 5, lane = t & 31;
    __shared__ float2 s_st[8][4];
    __shared__ float2 s_mr[4];
    __shared__ float  s_sim[4][8][16];

    ull wq2[8][4];
#pragma unroll
    for (int j = 0; j < 8; j++) {
        const ulonglong2* p = (const ulonglong2*)(g_wqp + j * 1024 + 4 * t);
        ulonglong2 p0 = p[0], p1 = p[1];
        wq2[j][0] = p0.x; wq2[j][1] = p0.y; wq2[j][2] = p1.x; wq2[j][3] = p1.y;
    }
    float4 g4 = __ldg((const float4*)ng + t);
    float4 b4 = __ldg((const float4*)nb + t);

    int rowblock = blockIdx.x * 32;
    const float4* xb = (const float4*)x + (size_t)rowblock * 256;

    for (int it = 0; it < 8; it++) {
        float4 v[4];
#pragma unroll
        for (int r = 0; r < 4; r++) v[r] = xb[(size_t)(it * 4 + r) * 256 + t];
#pragma unroll
        for (int r = 0; r < 4; r++) {
            float sm = v[r].x + v[r].y + v[r].z + v[r].w;
            float sq = v[r].x * v[r].x + v[r].y * v[r].y + v[r].z * v[r].z + v[r].w * v[r].w;
#pragma unroll
            for (int k = 16; k >= 1; k >>= 1) {
                sm += __shfl_xor_sync(0xffffffffu, sm, k);
                sq += __shfl_xor_sync(0xffffffffu, sq, k);
            }
            if (lane == 0) s_st[w][r] = make_float2(sm, sq);
        }
        __syncthreads();
        if (t < 4) {
            float S = 0.f, Q = 0.f;
#pragma unroll
            for (int w2 = 0; w2 < 8; w2++) { S += s_st[w2][t].x; Q += s_st[w2][t].y; }
            float m = S * (1.0f / 1024.0f);
            float var = Q * (1.0f / 1024.0f) - m * m;
            s_mr[t] = make_float2(m, rsqrtf(var + 1e-5f));
        }
        __syncthreads();

#pragma unroll
        for (int r = 0; r < 4; r++) {
            float mu = s_mr[r].x, rs = s_mr[r].y;
            float x0 = (v[r].x - mu) * rs * g4.x + b4.x;
            float x1 = (v[r].y - mu) * rs * g4.y + b4.y;
            float x2 = (v[r].z - mu) * rs * g4.z + b4.z;
            float x3 = (v[r].w - mu) * rs * g4.w + b4.w;

            size_t row = (size_t)rowblock + it * 4 + r;
            __half2 p01 = __floats2half2_rn(x0, x1);
            __half2 p23 = __floats2half2_rn(x2, x3);
            uint2 pk;
            pk.x = *reinterpret_cast<unsigned*>(&p01);
            pk.y = *reinterpret_cast<unsigned*>(&p23);
            *reinterpret_cast<uint2*>(g_xn + row * 1024 + 4 * t) = pk;

            ull xd0 = fdup(x0), xd1 = fdup(x1), xd2 = fdup(x2), xd3 = fdup(x3);
            float acc[16];
#pragma unroll
            for (int j = 0; j < 8; j++) {
                ull a = ffma2(xd0, wq2[j][0], 0ull);
                a = ffma2(xd1, wq2[j][1], a);
                a = ffma2(xd2, wq2[j][2], a);
                a = ffma2(xd3, wq2[j][3], a);
                funpack(a, acc[2 * j], acc[2 * j + 1]);
            }
            bstep<8>(acc, lane);
            bstep<4>(acc, lane);
            bstep<2>(acc, lane);
            bstep<1>(acc, lane);
            acc[0] += __shfl_xor_sync(0xffffffffu, acc[0], 16);
            if (lane < 16) s_sim[r][w][lane] = acc[0];
        }
        __syncthreads();

        if (t < 64) {
            int r = t >> 4, h = t & 15;
            float val = 0.f;
#pragma unroll
            for (int w2 = 0; w2 < 8; w2++) val += s_sim[r][w2][h];
            int row = rowblock + it * 4 + r;
            int b = row >> 12, s = row & 4095;
            g_sim[((size_t)(b * 16 + h)) * 4096 + s] = val + g_kdot[h];
        }
    }
}

// ---------------- K2a: per (b,h) softmax stats {max, 1/sum} ----------------
__global__ void k_sm1() {
    int bh = blockIdx.x, t = threadIdx.x, w = t >> 5, lane = t & 31;
    const float* sr = g_sim + (size_t)bh * 4096;
    float v[16];
    float mx = -1e30f;
#pragma unroll
    for (int k = 0; k < 16; k++) { v[k] = sr[k * 256 + t]; mx = fmaxf(mx, v[k]); }
#pragma unroll
    for (int k = 16; k >= 1; k >>= 1) mx = fmaxf(mx, __shfl_xor_sync(0xffffffffu, mx, k));
    __shared__ float red[8];
    if (lane == 0) red[w] = mx;
    __syncthreads();
    float bm = red[0];
#pragma unroll
    for (int i = 1; i < 8; i++) bm = fmaxf(bm, red[i]);
    __syncthreads();
    float s = 0.f;
#pragma unroll
    for (int k = 0; k < 16; k++) s += __expf(v[k] - bm);
#pragma unroll
    for (int k = 16; k >= 1; k >>= 1) s += __shfl_xor_sync(0xffffffffu, s, k);
    if (lane == 0) red[w] = s;
    __syncthreads();
    if (t == 0) {
        float tot = 0.f;
#pragma unroll
        for (int i = 0; i < 8; i++) tot += red[i];
        g_minv[bh] = make_float2(bm, 1.0f / tot);
    }
}

// ---------------- K2b: probs — thread owns one s, all 16 h in regs ----------------
// Both attn (per-h coalesced) and att2 [b][s][h] (contiguous 128B/thread) coalesce.
__global__ void k_sm2(float* __restrict__ attn_out) {
    int b = blockIdx.x >> 4, sc = blockIdx.x & 15;
    int t = threadIdx.x;
    int s = sc * 256 + t;
    float2 mi[16];
#pragma unroll
    for (int h = 0; h < 16; h++) mi[h] = g_minv[b * 16 + h];
    float pv[16];
#pragma unroll
    for (int h = 0; h < 16; h++) {
        float val = __ldg(g_sim + ((size_t)(b * 16 + h)) * 4096 + s);
        float p = __expf(val - mi[h].x) * mi[h].y;
        pv[h] = p;
        attn_out[((size_t)(b * 16 + h)) * 4096 + s] = p;
    }
    float4* a4 = (float4*)(g_att2 + ((size_t)(b * 4096 + s)) * 16);
#pragma unroll
    for (int k = 0; k < 8; k++)
        a4[k] = make_float4(pv[2 * k], pv[2 * k], pv[2 * k + 1], pv[2 * k + 1]);
}

// ---------------- K3: y_part[ch][b][h][d] = sum_{s in 128-chunk} attn * xn ---------
// grid 256 = b(8) x ch(32); thread owns 4 cols, all 16 heads (xn read once).
__global__ __launch_bounds__(256) void k_y() {
    int b = blockIdx.x >> 5, ch = blockIdx.x & 31;
    int t = threadIdx.x;
    int s0 = ch * 128;
    const __half* xrow = g_xn + ((size_t)(b * 4096 + s0)) * 1024 + 4 * t;
    const ulonglong2* attb = (const ulonglong2*)(g_att2 + ((size_t)(b * 4096 + s0)) * 16);
    ull accA[16], accB[16];
#pragma unroll
    for (int h = 0; h < 16; h++) { accA[h] = 0ull; accB[h] = 0ull; }
#pragma unroll 2
    for (int s = 0; s < 128; s++) {
        uint2 px = *reinterpret_cast<const uint2*>(xrow + (size_t)s * 1024);
        __half2 h01 = *reinterpret_cast<__half2*>(&px.x);
        __half2 h23 = *reinterpret_cast<__half2*>(&px.y);
        float2 f01 = __half22float2(h01), f23 = __half22float2(h23);
        ull x01 = fpack(f01.x, f01.y), x23 = fpack(f23.x, f23.y);
#pragma unroll
        for (int j = 0; j < 8; j++) {
            ulonglong2 u = __ldg(&attb[(size_t)s * 8 + j]);
            accA[2 * j]     = ffma2(x01, u.x, accA[2 * j]);
            accB[2 * j]     = ffma2(x23, u.x, accB[2 * j]);
            accA[2 * j + 1] = ffma2(x01, u.y, accA[2 * j + 1]);
            accB[2 * j + 1] = ffma2(x23, u.y, accB[2 * j + 1]);
        }
    }
    float* yp = g_ypart + ((size_t)(ch * 8 + b) * 16) * 1024 + 4 * t;
#pragma unroll
    for (int h = 0; h < 16; h++) {
        float4 o;
        funpack(accA[h], o.x, o.y);
        funpack(accB[h], o.z, o.w);
        *reinterpret_cast<float4*>(yp + (size_t)h * 1024) = o;
    }
}

// ---------------- K3r: reduce 32 s-chunk partials ----------------
__global__ void k_yred() {
    int i4 = blockIdx.x * 256 + threadIdx.x;  // 32768 float4
    float4 acc = make_float4(0.f, 0.f, 0.f, 0.f);
#pragma unroll
    for (int c = 0; c < 32; c++) {
        float4 v = ((const float4*)g_ypart)[(size_t)c * 32768 + i4];
        acc.x += v.x; acc.y += v.y; acc.z += v.z; acc.w += v.w;
    }
    ((float4*)g_y)[i4] = acc;
}

// ---------------- K4: oh_part[dc][b][h][dh] = sum_{d in 128-chunk} y*Wv ------------
__global__ void k_oh(const float* __restrict__ Wkv) {
    int t = threadIdx.x, w = t >> 5, lane = t & 31;
    int wg = blockIdx.x * 8 + w;  // 0..1023
    int dc = wg >> 7;
    int bh = wg & 127;
    int h = bh & 15;
    const float* yrow = g_y + (size_t)bh * 1024 + dc * 128;
    const float* wvb = Wkv + 1024 + h * 64 + lane * 2 + (size_t)(dc * 128) * 2048;
    float2 acc = make_float2(0.f, 0.f);
#pragma unroll 8
    for (int d = 0; d < 128; d++) {
        float yv = __ldg(yrow + d);
        float2 wv = *reinterpret_cast<const float2*>(wvb + (size_t)d * 2048);
        acc.x += yv * wv.x;
        acc.y += yv * wv.y;
    }
    *reinterpret_cast<float2*>(g_ohp + (size_t)(dc * 128 + bh) * 64 + lane * 2) = acc;
}

// ---------------- K5: out partials (fused ohp reduce + bias) ----------------
__global__ void k_outp(const float* __restrict__ Wout, const float* __restrict__ bkv) {
    __shared__ float s_oh[8][128];
    int t = threadIdx.x;
    int dblk = blockIdx.x >> 3, ic = blockIdx.x & 7;
    {
        int bb = t >> 5, j = t & 31;
#pragma unroll
        for (int k = 0; k < 4; k++) {
            int ii = ic * 128 + j * 4 + k;
            int h = ii >> 6, dh = ii & 63;
            float v = 0.f;
#pragma unroll
            for (int dc = 0; dc < 8; dc++)
                v += g_ohp[(size_t)(dc * 128 + bb * 16 + h) * 64 + dh];
            v += __ldg(bkv + 1024 + ii);  // V bias passes through (attn sums to 1)
            s_oh[bb][j * 4 + k] = v;
        }
    }
    __syncthreads();
    int b = t >> 5, dl = t & 31;
    int d = dblk * 32 + dl;
    const float* wb = Wout + (size_t)(ic * 128) * 1024 + d;
    float acc = 0.f;
#pragma unroll 8
    for (int i = 0; i < 128; i++) acc += s_oh[b][i] * __ldg(wb + (size_t)i * 1024);
    g_outp[(size_t)(ic * 8 + b) * 1024 + d] = acc;
}

// ---------------- K5r: out[b][d] = sum_ic outp + bout ----------------
__global__ void k_outred(const float* __restrict__ bout, float* __restrict__ out) {
    int idx = blockIdx.x * 256 + threadIdx.x;  // 8192
    int b = idx >> 10, d = idx & 1023;
    float v = 0.f;
#pragma unroll
    for (int ic = 0; ic < 8; ic++) v += g_outp[(size_t)(ic * 8 + b) * 1024 + d];
    out[idx] = v + __ldg(bout + d);
}

// ---------------- launch ----------------
extern "C" void kernel_launch(void* const* d_in, const int* in_sizes, int n_in,
                              void* d_out, int out_size) {
    const float* x    = (const float*)d_in[0];
    const float* q    = (const float*)d_in[1];
    const float* Wkv  = (const float*)d_in[2];
    const float* bkv  = (const float*)d_in[3];
    const float* Wout = (const float*)d_in[4];
    const float* bout = (const float*)d_in[5];
    const float* ng   = (const float*)d_in[6];
    const float* nb   = (const float*)d_in[7];
    const float* qg   = (const float*)d_in[8];
    const float* qb   = (const float*)d_in[9];
    float* out = (float*)d_out;          // [8,1,1024]
    float* attn = out + 8192;            // [8,16,1,4096]

    k_qn<<<1, 512>>>(q, qg, qb, bkv);
    k_wq<<<128, 256>>>(Wkv);
    k_main<<<1024, 256>>>(x, ng, nb);
    k_sm1<<<128, 256>>>();
    k_sm2<<<128, 256>>>(attn);
    k_y<<<256, 256>>>();
    k_yred<<<128, 256>>>();
    k_oh<<<128, 256>>>(Wkv);
    k_outp<<<256, 256>>>(Wout, bkv);
    k_outred<<<32, 256>>>(bout, out);
}